// round 7
// baseline (speedup 1.0000x reference)
#include <cuda_runtime.h>
#include <math.h>

// Problem constants
#define NN 100000
#define EE 1600000
#define KDIM 128
#define HF 64          // HEADS * OUT_FEAT
#define NHEADS 4
#define ALPHA 0.2f

typedef unsigned long long u64;

// ---------------- scratch (device globals; no allocation allowed) ----------
__device__ float g_h[NN * HF];          // 25.6 MB
__device__ float g_att_src[NN * NHEADS];
__device__ float g_att_dst[NN * NHEADS];
__device__ int   g_deg[NN];
__device__ int   g_off[NN + 1];
__device__ int   g_cursor[NN];
__device__ int   g_csr[EE];
__device__ int   g_bsum[128];
__device__ int   g_is64;                // 1 if edge_index is int64-laid-out

// ---------------- f32x2 packed-FMA helpers (PTX-only; ptxas won't fuse) ----
__device__ __forceinline__ u64 pack2(float x) {
    u64 r;
    asm("mov.b64 %0, {%1, %1};" : "=l"(r) : "r"(__float_as_uint(x)));
    return r;
}
__device__ __forceinline__ void ffma2(u64& acc, u64 a, u64 b) {
    asm("fma.rn.f32x2 %0, %1, %2, %0;" : "+l"(acc) : "l"(a), "l"(b));
}
__device__ __forceinline__ float2 unpack2(u64 v) {
    unsigned lo, hi;
    asm("mov.b64 {%0, %1}, %2;" : "=r"(lo), "=r"(hi) : "l"(v));
    return make_float2(__uint_as_float(lo), __uint_as_float(hi));
}

// ---------------- K0: zero degree histogram + detect edge dtype ------------
// int64 little-endian values < 2^31  =>  every odd 32-bit word is 0.
__global__ void init_kernel(const int* __restrict__ ew) {
    int i = blockIdx.x * blockDim.x + threadIdx.x;
    if (i < NN) g_deg[i] = 0;
    if (blockIdx.x == 0) {
        __shared__ int s_any;
        if (threadIdx.x == 0) s_any = 0;
        __syncthreads();
        int v = ew[2 * (threadIdx.x * 997 + 1) + 1];   // sample odd words
        unsigned nz = __ballot_sync(0xFFFFFFFFu, v != 0);
        if (nz && (threadIdx.x & 31) == 0) atomicOr(&s_any, 1);
        __syncthreads();
        if (threadIdx.x == 0) g_is64 = s_any ? 0 : 1;
    }
}

// ---------------- K1: GEMM  h = x @ W  (f32x2) + fused att-logit epilogue --
// 64x64 block tile, 4 rows x 2 col-pairs per thread, 256 threads/block.
__global__ __launch_bounds__(256) void gemm_kernel(const float* __restrict__ X,
                                                   const float* __restrict__ W,
                                                   const float* __restrict__ Asrc,
                                                   const float* __restrict__ Adst) {
    __shared__ float Xs[32][68];   // [k][row], 272B pitch (16B multiple)
    __shared__ float Ws[32][64];   // [k][col], 256B pitch

    const int block_row = blockIdx.x * 64;
    const int tx = threadIdx.x & 15;        // col group: 4 cols = 2 pairs
    const int ty = threadIdx.x >> 4;        // row group: 4 rows
    const int lane = threadIdx.x & 31;
    const int wrp  = threadIdx.x >> 5;

    u64 acc2[4][2];
#pragma unroll
    for (int i = 0; i < 4; i++) { acc2[i][0] = 0ULL; acc2[i][1] = 0ULL; }

    for (int k0 = 0; k0 < KDIM; k0 += 32) {
#pragma unroll
        for (int r = 0; r < 8; r++) {
            int row = wrp * 8 + r;
            int gr  = block_row + row;
            float v = 0.0f;
            if (gr < NN) v = X[(long)gr * KDIM + k0 + lane];
            Xs[lane][row] = v;
        }
#pragma unroll
        for (int i = 0; i < 8; i++) {
            int idx = threadIdx.x + i * 256;
            int kk = idx >> 6, cc = idx & 63;
            Ws[kk][cc] = W[(k0 + kk) * HF + cc];
        }
        __syncthreads();

#pragma unroll
        for (int k = 0; k < 32; k++) {
            ulonglong2 wp = *(const ulonglong2*)&Ws[k][tx * 4];  // {w0w1, w2w3}
            float4 xv = *(const float4*)&Xs[k][ty * 4];
            u64 x0 = pack2(xv.x), x1 = pack2(xv.y);
            u64 x2 = pack2(xv.z), x3 = pack2(xv.w);
            ffma2(acc2[0][0], x0, wp.x); ffma2(acc2[0][1], x0, wp.y);
            ffma2(acc2[1][0], x1, wp.x); ffma2(acc2[1][1], x1, wp.y);
            ffma2(acc2[2][0], x2, wp.x); ffma2(acc2[2][1], x2, wp.y);
            ffma2(acc2[3][0], x3, wp.x); ffma2(acc2[3][1], x3, wp.y);
        }
        __syncthreads();
    }

    // epilogue: write h tile + fused attention logits
    float as_r[4], ad_r[4];
#pragma unroll
    for (int j = 0; j < 4; j++) {
        as_r[j] = Asrc[tx * 4 + j];
        ad_r[j] = Adst[tx * 4 + j];
    }
    const int head = tx >> 2;

#pragma unroll
    for (int i = 0; i < 4; i++) {
        int gr = block_row + ty * 4 + i;
        float2 c01 = unpack2(acc2[i][0]);
        float2 c23 = unpack2(acc2[i][1]);
        float ps = c01.x * as_r[0] + c01.y * as_r[1]
                 + c23.x * as_r[2] + c23.y * as_r[3];
        float pd = c01.x * ad_r[0] + c01.y * ad_r[1]
                 + c23.x * ad_r[2] + c23.y * ad_r[3];
        ps += __shfl_xor_sync(0xFFFFFFFFu, ps, 1);
        ps += __shfl_xor_sync(0xFFFFFFFFu, ps, 2);
        pd += __shfl_xor_sync(0xFFFFFFFFu, pd, 1);
        pd += __shfl_xor_sync(0xFFFFFFFFu, pd, 2);
        if (gr < NN) {
            float4 v = make_float4(c01.x, c01.y, c23.x, c23.y);
            *(float4*)&g_h[(long)gr * HF + tx * 4] = v;
            if ((lane & 3) == 0) {
                g_att_src[gr * 4 + head] = ps;
                g_att_dst[gr * 4 + head] = pd;
            }
        }
    }
}

// ---------------- K2: dst histogram (reads edge_index directly) ------------
__global__ void hist_kernel(const int* __restrict__ ew) {
    int e = blockIdx.x * blockDim.x + threadIdx.x;
    if (e >= EE) return;
    int d = g_is64 ? ew[2 * EE + 2 * e] : ew[EE + e];
    d = min(max(d, 0), NN - 1);
    atomicAdd(&g_deg[d], 1);
}

// ---------------- K3a: per-1024-block exclusive scan of degrees ------------
__global__ void scanA_kernel() {
    __shared__ int sh[1024];
    int i = blockIdx.x * 1024 + threadIdx.x;
    int v = (i < NN) ? g_deg[i] : 0;
    sh[threadIdx.x] = v;
    __syncthreads();
#pragma unroll
    for (int s = 1; s < 1024; s <<= 1) {
        int t = 0;
        if ((int)threadIdx.x >= s) t = sh[threadIdx.x - s];
        __syncthreads();
        if ((int)threadIdx.x >= s) sh[threadIdx.x] += t;
        __syncthreads();
    }
    if (i < NN) g_off[i] = sh[threadIdx.x] - v;   // exclusive within block
    if (threadIdx.x == 1023) g_bsum[blockIdx.x] = sh[1023];
}

// ---------------- K3b: fixup (each block redundantly scans the 98 sums) ----
__global__ void scanC_kernel(int nblocks) {
    __shared__ int sb[128];
    const int t = threadIdx.x;
    int v = 0;
    if (t < 128) { v = (t < nblocks) ? g_bsum[t] : 0; sb[t] = v; }
    __syncthreads();
#pragma unroll
    for (int s = 1; s < 128; s <<= 1) {
        int add = 0;
        if (t < 128 && t >= s) add = sb[t - s];
        __syncthreads();
        if (t < 128 && t >= s) sb[t] += add;
        __syncthreads();
    }
    if (t < 128) sb[t] -= v;   // inclusive -> exclusive
    __syncthreads();
    int i = blockIdx.x * blockDim.x + t;
    if (i < NN) {
        int o = g_off[i] + sb[i >> 10];
        g_off[i] = o;
        g_cursor[i] = o;
    }
    if (i == 0) g_off[NN] = EE;
}

// ---------------- K4: scatter edges into CSR (grouped by dst) --------------
__global__ void scatter_kernel(const int* __restrict__ ew) {
    int e = blockIdx.x * blockDim.x + threadIdx.x;
    if (e >= EE) return;
    int s, d;
    if (g_is64) { s = ew[2 * e];  d = ew[2 * EE + 2 * e]; }
    else        { s = ew[e];      d = ew[EE + e]; }
    s = min(max(s, 0), NN - 1);
    d = min(max(d, 0), NN - 1);
    int p = atomicAdd(&g_cursor[d], 1);
    g_csr[p] = s;
}

// ---------------- K5: single-pass softmax + aggregation + ELU --------------
// One warp per destination node, software-pipelined x4 for MLP.
__global__ __launch_bounds__(256) void aggregate_kernel(float* __restrict__ out) {
    int warp = (blockIdx.x * blockDim.x + threadIdx.x) >> 5;
    int lane = threadIdx.x & 31;
    if (warp >= NN) return;
    const int n = warp;
    const int start = g_off[n];
    const int end   = g_off[n + 1];

    const int hh = lane >> 3;   // head of my two features
    const float adh = __ldg(&g_att_dst[n * 4 + hh]);

    float acc0 = 0.0f, acc1 = 0.0f, dsum = 0.0f;
    const float2* H2 = (const float2*)g_h;

    int j = start;
    const int n4 = start + ((end - start) & ~3);
    for (; j < n4; j += 4) {
        // issue all gathers before any compute -> 8+ loads in flight
        int s0 = g_csr[j], s1 = g_csr[j + 1], s2 = g_csr[j + 2], s3 = g_csr[j + 3];
        float a0 = __ldg(&g_att_src[s0 * 4 + hh]);
        float a1 = __ldg(&g_att_src[s1 * 4 + hh]);
        float a2 = __ldg(&g_att_src[s2 * 4 + hh]);
        float a3 = __ldg(&g_att_src[s3 * 4 + hh]);
        float2 h0 = __ldg(&H2[(long)s0 * 32 + lane]);
        float2 h1 = __ldg(&H2[(long)s1 * 32 + lane]);
        float2 h2 = __ldg(&H2[(long)s2 * 32 + lane]);
        float2 h3 = __ldg(&H2[(long)s3 * 32 + lane]);
        float e0 = a0 + adh; e0 = (e0 > 0.f) ? e0 : ALPHA * e0;
        float e1 = a1 + adh; e1 = (e1 > 0.f) ? e1 : ALPHA * e1;
        float e2 = a2 + adh; e2 = (e2 > 0.f) ? e2 : ALPHA * e2;
        float e3 = a3 + adh; e3 = (e3 > 0.f) ? e3 : ALPHA * e3;
        float w0 = __expf(e0), w1 = __expf(e1), w2 = __expf(e2), w3 = __expf(e3);
        dsum += (w0 + w1) + (w2 + w3);
        acc0 += w0 * h0.x + w1 * h1.x + w2 * h2.x + w3 * h3.x;
        acc1 += w0 * h0.y + w1 * h1.y + w2 * h2.y + w3 * h3.y;
    }
    for (; j < end; j++) {
        int s = g_csr[j];
        float ash = __ldg(&g_att_src[s * 4 + hh]);
        float e = ash + adh;
        e = (e > 0.f) ? e : ALPHA * e;
        float w = __expf(e);
        dsum += w;
        float2 hv = __ldg(&H2[(long)s * 32 + lane]);
        acc0 += w * hv.x;
        acc1 += w * hv.y;
    }

    float inv = 1.0f / (dsum + 1e-16f);
    float o0 = acc0 * inv, o1 = acc1 * inv;
    o0 = (o0 > 0.f) ? o0 : expm1f(o0);   // jax.nn.elu
    o1 = (o1 > 0.f) ? o1 : expm1f(o1);
    *(float2*)&out[(long)n * HF + 2 * lane] = make_float2(o0, o1);
}

// ---------------- launch ----------------------------------------------------
extern "C" void kernel_launch(void* const* d_in, const int* in_sizes, int n_in,
                              void* d_out, int out_size) {
    const float* x     = (const float*)d_in[0];
    const int*   ew    = (const int*)d_in[1];   // edge_index words
    const float* W     = (const float*)d_in[2];
    const float* a_src = (const float*)d_in[3];
    const float* a_dst = (const float*)d_in[4];
    float* out = (float*)d_out;

    (void)in_sizes; (void)n_in; (void)out_size;

    static cudaStream_t s2 = 0;
    static cudaEvent_t  evA = 0, evB = 0;
    static int tried = 0;
    if (!tried) {
        tried = 1;
        if (cudaStreamCreateWithFlags(&s2, cudaStreamNonBlocking) != cudaSuccess) s2 = 0;
        if (cudaEventCreateWithFlags(&evA, cudaEventDisableTiming) != cudaSuccess) evA = 0;
        if (cudaEventCreateWithFlags(&evB, cudaEventDisableTiming) != cudaSuccess) evB = 0;
    }
    const bool overlap = (s2 && evA && evB);

    const int NB = (NN + 1023) / 1024;   // 98

    init_kernel<<<(NN + 255) / 256, 256>>>(ew);

    if (overlap) {
        cudaEventRecord(evA, 0);
        cudaStreamWaitEvent(s2, evA, 0);
        hist_kernel<<<(EE + 255) / 256, 256, 0, s2>>>(ew);
        scanA_kernel<<<NB, 1024, 0, s2>>>();
        scanC_kernel<<<(NN + 255) / 256, 256, 0, s2>>>(NB);
        scatter_kernel<<<(EE + 255) / 256, 256, 0, s2>>>(ew);
        cudaEventRecord(evB, s2);
        gemm_kernel<<<(NN + 63) / 64, 256>>>(x, W, a_src, a_dst);
        cudaStreamWaitEvent(0, evB, 0);
    } else {
        hist_kernel<<<(EE + 255) / 256, 256>>>(ew);
        scanA_kernel<<<NB, 1024>>>();
        scanC_kernel<<<(NN + 255) / 256, 256>>>(NB);
        scatter_kernel<<<(EE + 255) / 256, 256>>>(ew);
        gemm_kernel<<<(NN + 63) / 64, 256>>>(x, W, a_src, a_dst);
    }

    aggregate_kernel<<<(NN * 32 + 255) / 256, 256>>>(out);
}

// round 9
// speedup vs baseline: 1.4668x; 1.4668x over previous
#include <cuda_runtime.h>
#include <math.h>

// Problem constants
#define NN 100000
#define EE 1600000
#define KDIM 128
#define HF 64          // HEADS * OUT_FEAT
#define NHEADS 4
#define ALPHA 0.2f

// ---------------- scratch (device globals; no allocation allowed) ----------
__device__ float g_h[NN * HF];          // 25.6 MB
__device__ float g_att_src[NN * NHEADS];
__device__ float g_att_dst[NN * NHEADS];
__device__ int   g_deg[NN];
__device__ int   g_off[NN + 1];
__device__ int   g_cursor[NN];
__device__ int   g_csr[EE];
__device__ int   g_bsum[128];
__device__ int   g_is64;                // 1 if edge_index is int64-laid-out

// ---------------- K0: zero degree histogram + detect edge dtype ------------
// int64 little-endian values < 2^31  =>  every odd 32-bit word is 0.
__global__ void init_kernel(const int* __restrict__ ew) {
    int i = blockIdx.x * blockDim.x + threadIdx.x;
    if (i < NN) g_deg[i] = 0;
    if (blockIdx.x == 0) {
        __shared__ int s_any;
        if (threadIdx.x == 0) s_any = 0;
        __syncthreads();
        int v = ew[2 * (threadIdx.x * 997 + 1) + 1];   // sample odd words
        unsigned nz = __ballot_sync(0xFFFFFFFFu, v != 0);
        if (nz && (threadIdx.x & 31) == 0) atomicOr(&s_any, 1);
        __syncthreads();
        if (threadIdx.x == 0) g_is64 = s_any ? 0 : 1;
    }
}

// ---------------- K1: GEMM  h = x @ W  + fused attention-logit epilogue ----
// EXACT R6 version (measured inside the 143.9us run). 64x64 block tile,
// 4x4 micro-tile per thread, scalar float4 FMA, 256 threads/block.
__global__ __launch_bounds__(256) void gemm_kernel(const float* __restrict__ X,
                                                   const float* __restrict__ W,
                                                   const float* __restrict__ Asrc,
                                                   const float* __restrict__ Adst) {
    __shared__ float Xs[32][68];   // [k][row], padded row pitch
    __shared__ float Ws[32][64];   // [k][col]

    const int block_row = blockIdx.x * 64;
    const int tx = threadIdx.x & 15;        // 0..15 -> 4 cols each
    const int ty = threadIdx.x >> 4;        // 0..15 -> 4 rows each
    const int lane = threadIdx.x & 31;
    const int wrp  = threadIdx.x >> 5;      // 0..7

    float acc[4][4];
#pragma unroll
    for (int i = 0; i < 4; i++)
#pragma unroll
        for (int j = 0; j < 4; j++) acc[i][j] = 0.0f;

    for (int k0 = 0; k0 < KDIM; k0 += 32) {
#pragma unroll
        for (int r = 0; r < 8; r++) {
            int row = wrp * 8 + r;
            int gr  = block_row + row;
            float v = 0.0f;
            if (gr < NN) v = X[(long)gr * KDIM + k0 + lane];
            Xs[lane][row] = v;
        }
#pragma unroll
        for (int i = 0; i < 8; i++) {
            int idx = threadIdx.x + i * 256;
            int kk = idx >> 6, cc = idx & 63;
            Ws[kk][cc] = W[(k0 + kk) * HF + cc];
        }
        __syncthreads();

#pragma unroll
        for (int k = 0; k < 32; k++) {
            float4 xv = *(const float4*)&Xs[k][ty * 4];
            float4 wv = *(const float4*)&Ws[k][tx * 4];
            acc[0][0] += xv.x * wv.x; acc[0][1] += xv.x * wv.y;
            acc[0][2] += xv.x * wv.z; acc[0][3] += xv.x * wv.w;
            acc[1][0] += xv.y * wv.x; acc[1][1] += xv.y * wv.y;
            acc[1][2] += xv.y * wv.z; acc[1][3] += xv.y * wv.w;
            acc[2][0] += xv.z * wv.x; acc[2][1] += xv.z * wv.y;
            acc[2][2] += xv.z * wv.z; acc[2][3] += xv.z * wv.w;
            acc[3][0] += xv.w * wv.x; acc[3][1] += xv.w * wv.y;
            acc[3][2] += xv.w * wv.z; acc[3][3] += xv.w * wv.w;
        }
        __syncthreads();
    }

    // epilogue: write h tile + fused attention logits
    float as_r[4], ad_r[4];
#pragma unroll
    for (int j = 0; j < 4; j++) {
        as_r[j] = Asrc[tx * 4 + j];
        ad_r[j] = Adst[tx * 4 + j];
    }
    const int head = tx >> 2;   // 0..3

#pragma unroll
    for (int i = 0; i < 4; i++) {
        int gr = block_row + ty * 4 + i;
        float ps = acc[i][0] * as_r[0] + acc[i][1] * as_r[1]
                 + acc[i][2] * as_r[2] + acc[i][3] * as_r[3];
        float pd = acc[i][0] * ad_r[0] + acc[i][1] * ad_r[1]
                 + acc[i][2] * ad_r[2] + acc[i][3] * ad_r[3];
        ps += __shfl_xor_sync(0xFFFFFFFFu, ps, 1);
        ps += __shfl_xor_sync(0xFFFFFFFFu, ps, 2);
        pd += __shfl_xor_sync(0xFFFFFFFFu, pd, 1);
        pd += __shfl_xor_sync(0xFFFFFFFFu, pd, 2);
        if (gr < NN) {
            float4 v = make_float4(acc[i][0], acc[i][1], acc[i][2], acc[i][3]);
            *(float4*)&g_h[(long)gr * HF + tx * 4] = v;
            if ((lane & 3) == 0) {
                g_att_src[gr * 4 + head] = ps;
                g_att_dst[gr * 4 + head] = pd;
            }
        }
    }
}

// ---------------- K2: dst histogram (reads edge_index directly) ------------
__global__ void hist_kernel(const int* __restrict__ ew) {
    int e = blockIdx.x * blockDim.x + threadIdx.x;
    if (e >= EE) return;
    int d = g_is64 ? ew[2 * EE + 2 * e] : ew[EE + e];
    d = min(max(d, 0), NN - 1);
    atomicAdd(&g_deg[d], 1);
}

// ---------------- K3a: per-1024-block exclusive scan of degrees ------------
__global__ void scanA_kernel() {
    __shared__ int sh[1024];
    int i = blockIdx.x * 1024 + threadIdx.x;
    int v = (i < NN) ? g_deg[i] : 0;
    sh[threadIdx.x] = v;
    __syncthreads();
#pragma unroll
    for (int s = 1; s < 1024; s <<= 1) {
        int t = 0;
        if ((int)threadIdx.x >= s) t = sh[threadIdx.x - s];
        __syncthreads();
        if ((int)threadIdx.x >= s) sh[threadIdx.x] += t;
        __syncthreads();
    }
    if (i < NN) g_off[i] = sh[threadIdx.x] - v;   // exclusive within block
    if (threadIdx.x == 1023) g_bsum[blockIdx.x] = sh[1023];
}

// ---------------- K3b: fixup (each block redundantly scans the 98 sums) ----
__global__ void scanC_kernel(int nblocks) {
    __shared__ int sb[128];
    const int t = threadIdx.x;
    int v = 0;
    if (t < 128) { v = (t < nblocks) ? g_bsum[t] : 0; sb[t] = v; }
    __syncthreads();
#pragma unroll
    for (int s = 1; s < 128; s <<= 1) {
        int add = 0;
        if (t < 128 && t >= s) add = sb[t - s];
        __syncthreads();
        if (t < 128 && t >= s) sb[t] += add;
        __syncthreads();
    }
    if (t < 128) sb[t] -= v;   // inclusive -> exclusive
    __syncthreads();
    int i = blockIdx.x * blockDim.x + t;
    if (i < NN) {
        int o = g_off[i] + sb[i >> 10];
        g_off[i] = o;
        g_cursor[i] = o;
    }
    if (i == 0) g_off[NN] = EE;
}

// ---------------- K4: scatter edges into CSR (grouped by dst) --------------
__global__ void scatter_kernel(const int* __restrict__ ew) {
    int e = blockIdx.x * blockDim.x + threadIdx.x;
    if (e >= EE) return;
    int s, d;
    if (g_is64) { s = ew[2 * e];  d = ew[2 * EE + 2 * e]; }
    else        { s = ew[e];      d = ew[EE + e]; }
    s = min(max(s, 0), NN - 1);
    d = min(max(d, 0), NN - 1);
    int p = atomicAdd(&g_cursor[d], 1);
    g_csr[p] = s;
}

// ---------------- K5: single-pass softmax + aggregation + ELU --------------
// One warp per destination node, software-pipelined x4 for MLP.
__global__ __launch_bounds__(256) void aggregate_kernel(float* __restrict__ out) {
    int warp = (blockIdx.x * blockDim.x + threadIdx.x) >> 5;
    int lane = threadIdx.x & 31;
    if (warp >= NN) return;
    const int n = warp;
    const int start = g_off[n];
    const int end   = g_off[n + 1];

    const int hh = lane >> 3;   // head of my two features
    const float adh = __ldg(&g_att_dst[n * 4 + hh]);

    float acc0 = 0.0f, acc1 = 0.0f, dsum = 0.0f;
    const float2* H2 = (const float2*)g_h;

    int j = start;
    const int n4 = start + ((end - start) & ~3);
    for (; j < n4; j += 4) {
        int s0 = g_csr[j], s1 = g_csr[j + 1], s2 = g_csr[j + 2], s3 = g_csr[j + 3];
        float a0 = __ldg(&g_att_src[s0 * 4 + hh]);
        float a1 = __ldg(&g_att_src[s1 * 4 + hh]);
        float a2 = __ldg(&g_att_src[s2 * 4 + hh]);
        float a3 = __ldg(&g_att_src[s3 * 4 + hh]);
        float2 h0 = __ldg(&H2[(long)s0 * 32 + lane]);
        float2 h1 = __ldg(&H2[(long)s1 * 32 + lane]);
        float2 h2 = __ldg(&H2[(long)s2 * 32 + lane]);
        float2 h3 = __ldg(&H2[(long)s3 * 32 + lane]);
        float e0 = a0 + adh; e0 = (e0 > 0.f) ? e0 : ALPHA * e0;
        float e1 = a1 + adh; e1 = (e1 > 0.f) ? e1 : ALPHA * e1;
        float e2 = a2 + adh; e2 = (e2 > 0.f) ? e2 : ALPHA * e2;
        float e3 = a3 + adh; e3 = (e3 > 0.f) ? e3 : ALPHA * e3;
        float w0 = __expf(e0), w1 = __expf(e1), w2 = __expf(e2), w3 = __expf(e3);
        dsum += (w0 + w1) + (w2 + w3);
        acc0 += w0 * h0.x + w1 * h1.x + w2 * h2.x + w3 * h3.x;
        acc1 += w0 * h0.y + w1 * h1.y + w2 * h2.y + w3 * h3.y;
    }
    for (; j < end; j++) {
        int s = g_csr[j];
        float ash = __ldg(&g_att_src[s * 4 + hh]);
        float e = ash + adh;
        e = (e > 0.f) ? e : ALPHA * e;
        float w = __expf(e);
        dsum += w;
        float2 hv = __ldg(&H2[(long)s * 32 + lane]);
        acc0 += w * hv.x;
        acc1 += w * hv.y;
    }

    float inv = 1.0f / (dsum + 1e-16f);
    float o0 = acc0 * inv, o1 = acc1 * inv;
    o0 = (o0 > 0.f) ? o0 : expm1f(o0);   // jax.nn.elu
    o1 = (o1 > 0.f) ? o1 : expm1f(o1);
    *(float2*)&out[(long)n * HF + 2 * lane] = make_float2(o0, o1);
}

// ---------------- launch ----------------------------------------------------
extern "C" void kernel_launch(void* const* d_in, const int* in_sizes, int n_in,
                              void* d_out, int out_size) {
    const float* x     = (const float*)d_in[0];
    const int*   ew    = (const int*)d_in[1];   // edge_index words
    const float* W     = (const float*)d_in[2];
    const float* a_src = (const float*)d_in[3];
    const float* a_dst = (const float*)d_in[4];
    float* out = (float*)d_out;

    (void)in_sizes; (void)n_in; (void)out_size;

    static cudaStream_t s2 = 0;
    static cudaEvent_t  evA = 0, evB = 0;
    static int tried = 0;
    if (!tried) {
        tried = 1;
        if (cudaStreamCreateWithFlags(&s2, cudaStreamNonBlocking) != cudaSuccess) s2 = 0;
        if (cudaEventCreateWithFlags(&evA, cudaEventDisableTiming) != cudaSuccess) evA = 0;
        if (cudaEventCreateWithFlags(&evB, cudaEventDisableTiming) != cudaSuccess) evB = 0;
    }
    const bool overlap = (s2 && evA && evB);

    const int NB = (NN + 1023) / 1024;   // 98

    init_kernel<<<(NN + 255) / 256, 256>>>(ew);

    if (overlap) {
        cudaEventRecord(evA, 0);
        cudaStreamWaitEvent(s2, evA, 0);
        hist_kernel<<<(EE + 255) / 256, 256, 0, s2>>>(ew);
        scanA_kernel<<<NB, 1024, 0, s2>>>();
        scanC_kernel<<<(NN + 255) / 256, 256, 0, s2>>>(NB);
        scatter_kernel<<<(EE + 255) / 256, 256, 0, s2>>>(ew);
        cudaEventRecord(evB, s2);
        gemm_kernel<<<(NN + 63) / 64, 256>>>(x, W, a_src, a_dst);
        cudaStreamWaitEvent(0, evB, 0);
    } else {
        hist_kernel<<<(EE + 255) / 256, 256>>>(ew);
        scanA_kernel<<<NB, 1024>>>();
        scanC_kernel<<<(NN + 255) / 256, 256>>>(NB);
        scatter_kernel<<<(EE + 255) / 256, 256>>>(ew);
        gemm_kernel<<<(NN + 63) / 64, 256>>>(x, W, a_src, a_dst);
    }

    aggregate_kernel<<<(NN * 32 + 255) / 256, 256>>>(out);
}